// round 16
// baseline (speedup 1.0000x reference)
#include <cuda_runtime.h>
#include <cuda_fp16.h>
#include <cstdint>
#include <cstddef>

#define HS 1024
#define SQ 512
#define BA 128
#define NT 64

__device__ __half g_enc_h[(size_t)BA*SQ*HS];
__device__ __half g_UaK [(size_t)BA*SQ*HS];
__device__ __half g_Ua  [HS*HS];
__device__ __half g_W1  [4096*HS];     // [Wa_w ; W_hh]
__device__ float  g_b1  [4096];        // [Wa_b ; b_hh]
__device__ __half g_Wih [3072*HS];     // W_ih cols 3..1026 (ctx part)
__device__ float  g_W3  [3072*3];      // W_ih cols 0..2 (pred part)
__device__ __half g_hA  [BA*HS];
__device__ __half g_ctx [BA*HS];
__device__ float  g_gipre[BA*3072];    // b_ih + pred @ W3^T
__device__ float  g_qgh [BA*4096];     // [q | gh]
__device__ float  g_gi  [BA*3072];
__device__ float  g_h   [BA*HS];
__device__ unsigned g_bar[4*NT];       // grid-barrier counters (zeroed each replay)

// ---- math helpers ----
__device__ __forceinline__ float tanh_fast(float x){
    float y; asm("tanh.approx.f32 %0, %1;" : "=f"(y) : "f"(x)); return y;
}
__device__ __forceinline__ float tanh_precise(float x){
    float e = __expf(2.f*x);
    return 1.f - __fdividef(2.f, e + 1.f);
}
__device__ __forceinline__ float sigmoid_pf(float x){
    return __fdividef(1.f, 1.f + __expf(-x));
}
__device__ __forceinline__ void mma16816(float* d, const uint32_t* a, const uint32_t* b){
    asm volatile(
        "mma.sync.aligned.m16n8k16.row.col.f32.f16.f16.f32 "
        "{%0,%1,%2,%3}, {%4,%5,%6,%7}, {%8,%9}, {%0,%1,%2,%3};\n"
        : "+f"(d[0]), "+f"(d[1]), "+f"(d[2]), "+f"(d[3])
        : "r"(a[0]), "r"(a[1]), "r"(a[2]), "r"(a[3]), "r"(b[0]), "r"(b[1]));
}
__device__ __forceinline__ void cp16(void* dst, const void* src){
    uint32_t d = (uint32_t)__cvta_generic_to_shared(dst);
    asm volatile("cp.async.cg.shared.global [%0], [%1], 16;\n" :: "r"(d), "l"(src));
}
__device__ __forceinline__ void cp_commit(){ asm volatile("cp.async.commit_group;\n"); }
template<int Np>
__device__ __forceinline__ void cp_wait(){ asm volatile("cp.async.wait_group %0;\n" :: "n"(Np)); }

// ---- software grid barrier: RMW arrive, RMW poll, trailing fence (R14-proven) ----
__device__ __forceinline__ void gsync(int idx){
    __syncthreads();
    if (threadIdx.x == 0){
        __threadfence();
        atomicAdd(&g_bar[idx], 1u);
        while (atomicAdd(&g_bar[idx], 0u) < (unsigned)BA) { }
        __threadfence();
    }
    __syncthreads();
}

// ---- 64x64 GEMM phase, 4-stage cp.async, ALL 512 threads (16 warps, 32x8 warp tile) ----
template<int MODE>
__device__ __forceinline__ void gemm_phase(bool act,
    const __half* __restrict__ A, const __half* __restrict__ Bm,
    float* __restrict__ Cb, const float* __restrict__ bp,
    int ldc, int bm, char* smraw)
{
    __half (*As)[64][40] = (__half(*)[64][40])smraw;
    __half (*Bs)[64][40] = (__half(*)[64][40])(smraw + 20480);
    constexpr int K = HS;
    const int tid = threadIdx.x, lane = tid & 31, warp = tid >> 5;
    const int wm = warp >> 3, wn = warp & 7;
    const int g = lane >> 2, tc = lane & 3;
    const int lr = (tid & 255) >> 2, lc = (tid & 3) * 8;
    const bool loadA = tid < 256;

    float acc[2][4];
#pragma unroll
    for (int j=0;j<2;j++)
#pragma unroll
        for (int k=0;k<4;k++) acc[j][k] = 0.f;

    constexpr int iters = K >> 5;
    if (act){
#pragma unroll
        for (int p = 0; p < 3; p++){
            if (loadA) cp16(&As[p][lr][lc], &A [(size_t)(bm + lr)*K + p*32 + lc]);
            else       cp16(&Bs[p][lr][lc], &Bm[(size_t)lr*K        + p*32 + lc]);
            cp_commit();
        }
    }
    for (int i = 0; i < iters; i++){
        if (act){
            if (i + 3 < iters){
                const int sw = (i + 3) & 3;
                if (loadA) cp16(&As[sw][lr][lc], &A [(size_t)(bm + lr)*K + (i+3)*32 + lc]);
                else       cp16(&Bs[sw][lr][lc], &Bm[(size_t)lr*K        + (i+3)*32 + lc]);
                cp_commit();
                cp_wait<3>();
            } else {
                cp_wait<0>();
            }
        }
        __syncthreads();
        if (act){
            const int st = i & 3;
#pragma unroll
            for (int ks=0; ks<2; ks++){
                uint32_t af[2][4], bf[2];
                const int c0 = ks*16 + tc*2;
#pragma unroll
                for (int mt=0; mt<2; mt++){
                    int r0 = wm*32 + mt*16 + g;
                    af[mt][0] = *(const uint32_t*)&As[st][r0  ][c0];
                    af[mt][1] = *(const uint32_t*)&As[st][r0+8][c0];
                    af[mt][2] = *(const uint32_t*)&As[st][r0  ][c0+8];
                    af[mt][3] = *(const uint32_t*)&As[st][r0+8][c0+8];
                }
                {
                    int n0 = wn*8 + g;
                    bf[0] = *(const uint32_t*)&Bs[st][n0][c0];
                    bf[1] = *(const uint32_t*)&Bs[st][n0][c0+8];
                }
#pragma unroll
                for (int mt=0; mt<2; mt++)
                    mma16816(acc[mt], af[mt], bf);
            }
        }
        __syncthreads();
    }

    if (act){
#pragma unroll
        for (int mt=0; mt<2; mt++){
            int rr = bm + wm*32 + mt*16 + g;
            int cc = wn*8 + tc*2;
            if constexpr (MODE == 1){
                Cb[(size_t)rr*ldc + cc]       = acc[mt][0] + __ldcg(&bp[(size_t)rr*3072 + cc]);
                Cb[(size_t)rr*ldc + cc + 1]   = acc[mt][1] + __ldcg(&bp[(size_t)rr*3072 + cc + 1]);
                Cb[(size_t)(rr+8)*ldc + cc]   = acc[mt][2] + __ldcg(&bp[(size_t)(rr+8)*3072 + cc]);
                Cb[(size_t)(rr+8)*ldc + cc+1] = acc[mt][3] + __ldcg(&bp[(size_t)(rr+8)*3072 + cc + 1]);
            } else {
                float b0 = bp[cc], b1 = bp[cc+1];
                Cb[(size_t)rr*ldc + cc]       = acc[mt][0] + b0;
                Cb[(size_t)rr*ldc + cc + 1]   = acc[mt][1] + b1;
                Cb[(size_t)(rr+8)*ldc + cc]   = acc[mt][2] + b0;
                Cb[(size_t)(rr+8)*ldc + cc+1] = acc[mt][3] + b1;
            }
        }
    }
}

// ---- fully persistent decoder: all NT steps in one launch ----
__global__ void __launch_bounds__(512) k_all(
    const float* __restrict__ Va_w, const float* __restrict__ Va_b,
    const float* __restrict__ out_w, const float* __restrict__ out_b,
    const float* __restrict__ b_ih,
    float* __restrict__ pred_out, float* __restrict__ attn_out,
    float* __restrict__ hid_out)
{
    __shared__ __align__(16) char smraw[40960];
    __shared__ float rp[8][3];
    const int blk = blockIdx.x, tid = threadIdx.x;
    const int warp = tid >> 5, lane = tid & 31;

    for (int t = 0; t < NT; t++){

    // ---- P1: [q|gh] = hA @ W1^T + b1 ----
    {
        const int bn = (blk >> 1) * 64;
        const int bm = (blk & 1) * 64;
        gemm_phase<0>(true, g_hA, g_W1 + (size_t)bn*HS, g_qgh + bn, g_b1 + bn, 4096, bm, smraw);
    }
    gsync(4*t + 0);

    // ---- P2: fused flash-style attention: one pass over UaK+enc ----
    {
        float* qs  = (float*)smraw;           // 4KB
        float* va  = qs + HS;                 // 4KB
        float* sc  = va + HS;                 // 2KB
        float* smm = sc + SQ;                 // 64B
        float* sml = smm + 16;                // 64B
        float* tot = sml + 16;                // 4KB
        float (*part)[1024] = (float(*)[1024])(tot + 1024);  // 16KB  (total ~30.2KB)
        const int b = blk;
        for (int i = tid; i < HS; i += 512){
            qs[i] = __ldcg(&g_qgh[b*4096 + i]);
            va[i] = Va_w[i];
        }
        __syncthreads();

        const float vb = Va_b[0];
        const size_t rowbase = (size_t)b*SQ*HS;
        float m = -1e30f, l = 0.f;
        float c[4][8];
#pragma unroll
        for (int j = 0; j < 4; j++)
#pragma unroll
            for (int e = 0; e < 8; e++) c[j][e] = 0.f;

        for (int i = 0; i < 32; i++){
            const int s = warp*32 + i;
            const __half* up = g_UaK  + rowbase + (size_t)s*HS;
            const __half* ep = g_enc_h + rowbase + (size_t)s*HS;
            uint4 uv[4], ev[4];
#pragma unroll
            for (int j = 0; j < 4; j++){
                int h0 = j*256 + lane*8;
                uv[j] = *(const uint4*)(up + h0);
                ev[j] = *(const uint4*)(ep + h0);
            }
            float a0 = 0.f, a1 = 0.f, a2 = 0.f, a3 = 0.f;
#pragma unroll
            for (int j = 0; j < 4; j++){
                int h0 = j*256 + lane*8;
                const __half2* hp = (const __half2*)&uv[j];
                float4 qa  = *(const float4*)&qs[h0];
                float4 qb  = *(const float4*)&qs[h0+4];
                float4 va0 = *(const float4*)&va[h0];
                float4 va1 = *(const float4*)&va[h0+4];
                float2 f0 = __half22float2(hp[0]);
                float2 f1 = __half22float2(hp[1]);
                float2 f2 = __half22float2(hp[2]);
                float2 f3 = __half22float2(hp[3]);
                a0 += va0.x * tanh_fast(qa.x + f0.x);
                a1 += va0.y * tanh_fast(qa.y + f0.y);
                a2 += va0.z * tanh_fast(qa.z + f1.x);
                a3 += va0.w * tanh_fast(qa.w + f1.y);
                a0 += va1.x * tanh_fast(qb.x + f2.x);
                a1 += va1.y * tanh_fast(qb.y + f2.y);
                a2 += va1.z * tanh_fast(qb.z + f3.x);
                a3 += va1.w * tanh_fast(qb.w + f3.y);
            }
            float score = (a0 + a1) + (a2 + a3);
#pragma unroll
            for (int o = 16; o; o >>= 1) score += __shfl_xor_sync(0xffffffffu, score, o);
            score += vb;
            if (lane == 0) sc[s] = score;
            // online softmax update
            float mn  = fmaxf(m, score);
            float f   = __expf(m - mn);
            float wgt = __expf(score - mn);
            l = l*f + wgt;
#pragma unroll
            for (int j = 0; j < 4; j++){
                const __half2* hp = (const __half2*)&ev[j];
                float2 g0 = __half22float2(hp[0]);
                float2 g1 = __half22float2(hp[1]);
                float2 g2 = __half22float2(hp[2]);
                float2 g3 = __half22float2(hp[3]);
                c[j][0] = c[j][0]*f + wgt*g0.x;
                c[j][1] = c[j][1]*f + wgt*g0.y;
                c[j][2] = c[j][2]*f + wgt*g1.x;
                c[j][3] = c[j][3]*f + wgt*g1.y;
                c[j][4] = c[j][4]*f + wgt*g2.x;
                c[j][5] = c[j][5]*f + wgt*g2.y;
                c[j][6] = c[j][6]*f + wgt*g3.x;
                c[j][7] = c[j][7]*f + wgt*g3.y;
            }
            m = mn;
        }
        if (lane == 0){ smm[warp] = m; sml[warp] = l; }
        __syncthreads();

        float M = smm[0];
#pragma unroll
        for (int wI = 1; wI < 16; wI++) M = fmaxf(M, smm[wI]);
        float L = 0.f;
#pragma unroll
        for (int wI = 0; wI < 16; wI++) L += sml[wI] * __expf(smm[wI] - M);
        const float invL  = __fdividef(1.f, L);
        const float scale = __expf(m - M);      // per-warp (uniform across lanes)

        tot[tid] = 0.f; tot[tid + 512] = 0.f;
        __syncthreads();
#pragma unroll
        for (int r = 0; r < 4; r++){
            if ((warp >> 2) == r){
#pragma unroll
                for (int j = 0; j < 4; j++){
                    int h0 = j*256 + lane*8;
#pragma unroll
                    for (int e = 0; e < 8; e++) part[warp & 3][h0 + e] = scale * c[j][e];
                }
            }
            __syncthreads();
            {
                int h = tid;
                tot[h] += part[0][h] + part[1][h] + part[2][h] + part[3][h];
                h = tid + 512;
                tot[h] += part[0][h] + part[1][h] + part[2][h] + part[3][h];
            }
            __syncthreads();
        }

        attn_out[((size_t)b*NT + t)*SQ + tid] = __expf(sc[tid] - M) * invL;
        g_ctx[(size_t)b*HS + tid]       = __float2half_rn(tot[tid] * invL);
        g_ctx[(size_t)b*HS + tid + 512] = __float2half_rn(tot[tid + 512] * invL);
    }
    gsync(4*t + 1);

    // ---- P3: gi = ctx @ WihC^T + gi_pre (96 of 128 blocks) ----
    {
        const int b3 = (blk < 96) ? blk : 0;
        const int bm = (b3 / 48) * 64;
        const int bn = (b3 % 48) * 64;
        gemm_phase<1>(blk < 96, g_ctx, g_Wih + (size_t)bn*HS,
                      g_gi + bn, g_gipre + bn, 3072, bm, smraw);
    }
    gsync(4*t + 2);

    // ---- P4: GRU + prediction + next-step gi_pre ----
    {
        const int b = blk;
        if (tid < 256){
            float p0 = 0.f, p1 = 0.f, p2 = 0.f;
#pragma unroll
            for (int j = 0; j < 4; j++){
                int hh = tid + j*256;
                float ir = __ldcg(&g_gi[b*3072 + hh]);
                float iz = __ldcg(&g_gi[b*3072 + 1024 + hh]);
                float in = __ldcg(&g_gi[b*3072 + 2048 + hh]);
                float hr = __ldcg(&g_qgh[b*4096 + 1024 + hh]);
                float hz = __ldcg(&g_qgh[b*4096 + 2048 + hh]);
                float hn = __ldcg(&g_qgh[b*4096 + 3072 + hh]);
                float r = sigmoid_pf(ir + hr);
                float z = sigmoid_pf(iz + hz);
                float n = tanh_precise(in + r*hn);
                float hp = g_h[b*HS + hh];
                float hv = (1.f - z)*n + z*hp;
                g_h [b*HS + hh] = hv;
                g_hA[b*HS + hh] = __float2half_rn(hv);
                p0 += hv * out_w[hh];
                p1 += hv * out_w[1024 + hh];
                p2 += hv * out_w[2048 + hh];
            }
#pragma unroll
            for (int o = 16; o; o >>= 1){
                p0 += __shfl_xor_sync(0xffffffffu, p0, o);
                p1 += __shfl_xor_sync(0xffffffffu, p1, o);
                p2 += __shfl_xor_sync(0xffffffffu, p2, o);
            }
            if (lane == 0){ rp[warp][0] = p0; rp[warp][1] = p1; rp[warp][2] = p2; }
        }
        __syncthreads();
        if (tid < 256){
            float q0 = out_b[0], q1 = out_b[1], q2 = out_b[2];
#pragma unroll
            for (int w = 0; w < 8; w++){ q0 += rp[w][0]; q1 += rp[w][1]; q2 += rp[w][2]; }
            if (tid == 0){
                float mx = fmaxf(q0, fmaxf(q1, q2));
                float l2 = logf(__expf(q0-mx) + __expf(q1-mx) + __expf(q2-mx));
                float* po = pred_out + ((size_t)b*NT + t)*3;
                po[0] = q0 - mx - l2; po[1] = q1 - mx - l2; po[2] = q2 - mx - l2;
            }
#pragma unroll
            for (int j = 0; j < 12; j++){
                int n = tid + j*256;
                float w0 = g_W3[n*3], w1 = g_W3[n*3+1], w2 = g_W3[n*3+2];
                g_gipre[b*3072 + n] = b_ih[n] + q0*w0 + q1*w1 + q2*w2;
            }
        }
    }
    gsync(4*t + 3);

    } // t loop

    for (int i = tid; i < HS; i += 512)
        hid_out[blk*HS + i] = g_h[blk*HS + i];
}

// ---- one-time big GEMM: UaK = enc @ Ua^T + Ua_b ----
__global__ void __launch_bounds__(256) gemm_uak(const float* __restrict__ bias)
{
    __shared__ __half As[3][128][40];
    __shared__ __half Bs[3][128][40];
    const __half* A  = g_enc_h;
    const __half* Bm = g_Ua;

    const int bm = blockIdx.y * 128, bn = blockIdx.x * 128;
    const int tid = threadIdx.x, lane = tid & 31, warp = tid >> 5;
    const int wm = warp >> 1, wn = warp & 1;
    const int g = lane >> 2, tc = lane & 3;
    const int r0l = tid >> 2, cl = (tid & 3) * 8;

    float acc[2][8][4];
#pragma unroll
    for (int i=0;i<2;i++)
#pragma unroll
        for (int j=0;j<8;j++)
#pragma unroll
            for (int k=0;k<4;k++) acc[i][j][k] = 0.f;

    const int iters = HS >> 5;
#pragma unroll
    for (int p = 0; p < 2; p++){
        cp16(&As[p][r0l   ][cl], &A [(size_t)(bm + r0l   )*HS + p*32 + cl]);
        cp16(&As[p][r0l+64][cl], &A [(size_t)(bm + r0l+64)*HS + p*32 + cl]);
        cp16(&Bs[p][r0l   ][cl], &Bm[(size_t)(bn + r0l   )*HS + p*32 + cl]);
        cp16(&Bs[p][r0l+64][cl], &Bm[(size_t)(bn + r0l+64)*HS + p*32 + cl]);
        cp_commit();
    }

    int wr = 2;
    for (int i = 0; i < iters; i++){
        if (i + 2 < iters){
            cp16(&As[wr][r0l   ][cl], &A [(size_t)(bm + r0l   )*HS + (i+2)*32 + cl]);
            cp16(&As[wr][r0l+64][cl], &A [(size_t)(bm + r0l+64)*HS + (i+2)*32 + cl]);
            cp16(&Bs[wr][r0l   ][cl], &Bm[(size_t)(bn + r0l   )*HS + (i+2)*32 + cl]);
            cp16(&Bs[wr][r0l+64][cl], &Bm[(size_t)(bn + r0l+64)*HS + (i+2)*32 + cl]);
            cp_commit();
            cp_wait<2>();
            wr = (wr == 2) ? 0 : wr + 1;
        } else {
            cp_wait<0>();
        }
        __syncthreads();
        const int st = i % 3;
#pragma unroll
        for (int ks = 0; ks < 2; ks++){
            uint32_t af[2][4], bf[8][2];
            const int c0 = ks*16 + tc*2;
#pragma unroll
            for (int mt = 0; mt < 2; mt++){
                int rr = wm*32 + mt*16 + g;
                af[mt][0] = *(const uint32_t*)&As[st][rr  ][c0];
                af[mt][1] = *(const uint32_t*)&As[st][rr+8][c0];
                af[mt][2] = *(const uint32_t*)&As[st][rr  ][c0+8];
                af[mt][3] = *(const uint32_t*)&As[st][rr+8][c0+8];
            }
#pragma unroll
            for (int nt = 0; nt < 8; nt++){
                int n0 = wn*64 + nt*8 + g;
                bf[nt][0] = *(const uint32_t*)&Bs[st][n0][c0];
                bf[nt][1] = *(const uint32_t*)&Bs[st][n0][c0+8];
            }
#pragma unroll
            for (int mt = 0; mt < 2; mt++)
#pragma unroll
                for (int nt = 0; nt < 8; nt++)
                    mma16816(acc[mt][nt], af[mt], bf[nt]);
        }
        __syncthreads();
    }

#pragma unroll
    for (int mt = 0; mt < 2; mt++)
#pragma unroll
    for (int nt = 0; nt < 8; nt++){
        int r = bm + wm*32 + mt*16 + g;
        int c = bn + wn*64 + nt*8 + tc*2;
        float b0 = bias[c], b1 = bias[c+1];
        __half2* C = (__half2*)g_UaK;
        C[((size_t)r*HS + c) >> 1]     = __floats2half2_rn(acc[mt][nt][0] + b0, acc[mt][nt][1] + b1);
        C[((size_t)(r+8)*HS + c) >> 1] = __floats2half2_rn(acc[mt][nt][2] + b0, acc[mt][nt][3] + b1);
    }
}

// ---- init / conversion ----
__global__ void k_cvt_enc(const float4* __restrict__ src)
{
    const size_t n = (size_t)BA*SQ*HS/4;
    __half2* d = (__half2*)g_enc_h;
    for (size_t i = blockIdx.x*(size_t)blockDim.x + threadIdx.x; i < n;
         i += (size_t)gridDim.x*blockDim.x){
        float4 v = src[i];
        d[2*i]   = __floats2half2_rn(v.x, v.y);
        d[2*i+1] = __floats2half2_rn(v.z, v.w);
    }
}

__global__ void k_pack_weights(const float* __restrict__ Wa_w, const float* __restrict__ W_hh,
                               const float* __restrict__ Wa_b, const float* __restrict__ b_hh,
                               const float* __restrict__ W_ih, const float* __restrict__ Ua_w)
{
    const int idx = blockIdx.x*blockDim.x + threadIdx.x;
    const int stride = gridDim.x*blockDim.x;
    for (int i = idx; i < 4096*HS; i += stride){
        float v = (i < 1048576) ? Wa_w[i] : W_hh[i - 1048576];
        g_W1[i] = __float2half_rn(v);
    }
    for (int i = idx; i < 3072*HS; i += stride){
        int n = i >> 10, k = i & 1023;
        g_Wih[i] = __float2half_rn(W_ih[n*1027 + 3 + k]);
    }
    for (int i = idx; i < 3072*3; i += stride){
        int n = i / 3, j = i - n*3;
        g_W3[i] = W_ih[n*1027 + j];
    }
    for (int i = idx; i < HS*HS; i += stride) g_Ua[i] = __float2half_rn(Ua_w[i]);
    for (int i = idx; i < 4096; i += stride)  g_b1[i] = (i < 1024) ? Wa_b[i] : b_hh[i - 1024];
}

__global__ void k_init_state(const float* __restrict__ enc_hid, const float* __restrict__ b_ih)
{
    const int idx = blockIdx.x*blockDim.x + threadIdx.x;
    const int stride = gridDim.x*blockDim.x;
    for (int i = idx; i < BA*HS; i += stride){
        float v = enc_hid[i];
        g_h[i]  = v;
        g_hA[i] = __float2half_rn(v);
    }
    for (int i = idx; i < BA*3072; i += stride)
        g_gipre[i] = b_ih[i % 3072];           // pred = SOS = 0
    for (int i = idx; i < 4*NT; i += stride)
        g_bar[i] = 0u;                         // reset grid barriers every replay
}

extern "C" void kernel_launch(void* const* d_in, const int* in_sizes, int n_in,
                              void* d_out, int out_size)
{
    (void)in_sizes; (void)n_in; (void)out_size;
    const float* enc      = (const float*)d_in[0];
    const float* enc_hid  = (const float*)d_in[1];
    const float* Wa_w = (const float*)d_in[2];
    const float* Wa_b = (const float*)d_in[3];
    const float* Ua_w = (const float*)d_in[4];
    const float* Ua_b = (const float*)d_in[5];
    const float* Va_w = (const float*)d_in[6];
    const float* Va_b = (const float*)d_in[7];
    const float* W_ih = (const float*)d_in[8];
    const float* b_ih = (const float*)d_in[9];
    const float* W_hh = (const float*)d_in[10];
    const float* b_hh = (const float*)d_in[11];
    const float* out_w = (const float*)d_in[12];
    const float* out_b = (const float*)d_in[13];

    float* pred_out = (float*)d_out;                        // (B, NT, 3)
    float* hid_out  = pred_out + (size_t)BA*NT*3;           // (1, B, H)
    float* attn_out = hid_out  + (size_t)BA*HS;             // (B, NT, SQ)

    k_cvt_enc<<<1184, 256>>>((const float4*)enc);
    k_pack_weights<<<512, 256>>>(Wa_w, W_hh, Wa_b, b_hh, W_ih, Ua_w);
    k_init_state<<<128, 256>>>(enc_hid, b_ih);

    gemm_uak<<<dim3(HS/128, (BA*SQ)/128), 256>>>(Ua_b);

    k_all<<<BA, 512>>>(Va_w, Va_b, out_w, out_b, b_ih, pred_out, attn_out, hid_out);
}

// round 17
// speedup vs baseline: 1.1695x; 1.1695x over previous
#include <cuda_runtime.h>
#include <cuda_fp16.h>
#include <cstdint>
#include <cstddef>

#define HS 1024
#define SQ 512
#define BA 128
#define NT 64

__device__ __half g_enc_h[(size_t)BA*SQ*HS];
__device__ __half g_UaK [(size_t)BA*SQ*HS];
__device__ __half g_Ua  [HS*HS];
__device__ __half g_W1  [4096*HS];     // [Wa_w ; W_hh]
__device__ float  g_b1  [4096];        // [Wa_b ; b_hh]
__device__ __half g_Wih [3072*HS];     // W_ih cols 3..1026 (ctx part)
__device__ float  g_W3  [3072*3];      // W_ih cols 0..2 (pred part)
__device__ __half g_hA  [BA*HS];
__device__ __half g_ctx [BA*HS];
__device__ float  g_gipre[BA*3072];    // b_ih + pred @ W3^T
__device__ float  g_qgh [BA*4096];     // [q | gh]
__device__ float  g_gi  [BA*3072];
__device__ float  g_h   [BA*HS];
__device__ unsigned g_bar[3*NT];       // grid-barrier counters (zeroed each replay)

// ---- math helpers ----
__device__ __forceinline__ float tanh_fast(float x){
    float y; asm("tanh.approx.f32 %0, %1;" : "=f"(y) : "f"(x)); return y;
}
__device__ __forceinline__ float tanh_precise(float x){
    float e = __expf(2.f*x);
    return 1.f - __fdividef(2.f, e + 1.f);
}
__device__ __forceinline__ float sigmoid_pf(float x){
    return __fdividef(1.f, 1.f + __expf(-x));
}
__device__ __forceinline__ void mma16816(float* d, const uint32_t* a, const uint32_t* b){
    asm volatile(
        "mma.sync.aligned.m16n8k16.row.col.f32.f16.f16.f32 "
        "{%0,%1,%2,%3}, {%4,%5,%6,%7}, {%8,%9}, {%0,%1,%2,%3};\n"
        : "+f"(d[0]), "+f"(d[1]), "+f"(d[2]), "+f"(d[3])
        : "r"(a[0]), "r"(a[1]), "r"(a[2]), "r"(a[3]), "r"(b[0]), "r"(b[1]));
}
__device__ __forceinline__ void cp16(void* dst, const void* src){
    uint32_t d = (uint32_t)__cvta_generic_to_shared(dst);
    asm volatile("cp.async.cg.shared.global [%0], [%1], 16;\n" :: "r"(d), "l"(src));
}
__device__ __forceinline__ void cp_commit(){ asm volatile("cp.async.commit_group;\n"); }
template<int Np>
__device__ __forceinline__ void cp_wait(){ asm volatile("cp.async.wait_group %0;\n" :: "n"(Np)); }

// ---- software grid barrier (all BA blocks co-resident by construction) ----
__device__ __forceinline__ void gsync(int idx){
    __syncthreads();
    if (threadIdx.x == 0){
        __threadfence();
        atomicAdd(&g_bar[idx], 1u);
        while (atomicAdd(&g_bar[idx], 0u) < (unsigned)BA) { }
    }
    __syncthreads();
}

// ---- 64x64 GEMM phase, 4-stage cp.async, 256 active threads of 512 ----
// MODE 0: C = A@B^T + bias(bcast).  MODE 1: C = A@B^T + pre (per-elem, ld 3072, __ldcg).
template<int MODE>
__device__ __forceinline__ void gemm_phase(bool act,
    const __half* __restrict__ A, const __half* __restrict__ Bm,
    float* __restrict__ Cb, const float* __restrict__ bp,
    int ldc, int bm, char* smraw)
{
    __half (*As)[64][40] = (__half(*)[64][40])smraw;
    __half (*Bs)[64][40] = (__half(*)[64][40])(smraw + 20480);
    constexpr int K = HS;
    const int tid = threadIdx.x, lane = tid & 31, warp = tid >> 5;
    const int wm = (warp >> 2) & 1, wn = warp & 3;
    const int g = lane >> 2, tc = lane & 3;
    const int r = (tid >> 2) & 63, c = (tid & 3) * 8;

    float acc[2][2][4];
#pragma unroll
    for (int i=0;i<2;i++)
#pragma unroll
        for (int j=0;j<2;j++)
#pragma unroll
            for (int k=0;k<4;k++) acc[i][j][k] = 0.f;

    constexpr int iters = K >> 5;
    if (act){
#pragma unroll
        for (int p = 0; p < 3; p++){
            cp16(&As[p][r][c], &A [(size_t)(bm + r)*K + p*32 + c]);
            cp16(&Bs[p][r][c], &Bm[(size_t)r*K        + p*32 + c]);
            cp_commit();
        }
    }
    for (int i = 0; i < iters; i++){
        if (act){
            if (i + 3 < iters){
                const int sw = (i + 3) & 3;
                cp16(&As[sw][r][c], &A [(size_t)(bm + r)*K + (i+3)*32 + c]);
                cp16(&Bs[sw][r][c], &Bm[(size_t)r*K        + (i+3)*32 + c]);
                cp_commit();
                cp_wait<3>();
            } else {
                cp_wait<0>();
            }
        }
        __syncthreads();
        if (act){
            const int st = i & 3;
#pragma unroll
            for (int ks=0; ks<2; ks++){
                uint32_t af[2][4], bf[2][2];
                const int c0 = ks*16 + tc*2;
#pragma unroll
                for (int mt=0; mt<2; mt++){
                    int r0 = wm*32 + mt*16 + g;
                    af[mt][0] = *(const uint32_t*)&As[st][r0  ][c0];
                    af[mt][1] = *(const uint32_t*)&As[st][r0+8][c0];
                    af[mt][2] = *(const uint32_t*)&As[st][r0  ][c0+8];
                    af[mt][3] = *(const uint32_t*)&As[st][r0+8][c0+8];
                }
#pragma unroll
                for (int nt=0; nt<2; nt++){
                    int n0 = wn*16 + nt*8 + g;
                    bf[nt][0] = *(const uint32_t*)&Bs[st][n0][c0];
                    bf[nt][1] = *(const uint32_t*)&Bs[st][n0][c0+8];
                }
#pragma unroll
                for (int mt=0; mt<2; mt++)
#pragma unroll
                    for (int nt=0; nt<2; nt++)
                        mma16816(acc[mt][nt], af[mt], bf[nt]);
            }
        }
        __syncthreads();
    }

    if (act){
#pragma unroll
        for (int mt=0; mt<2; mt++)
#pragma unroll
        for (int nt=0; nt<2; nt++){
            int rr = bm + wm*32 + mt*16 + g;
            int cc = wn*16 + nt*8 + tc*2;
            if constexpr (MODE == 1){
                Cb[(size_t)rr*ldc + cc]       = acc[mt][nt][0] + bp[(size_t)rr*3072 + cc];
                Cb[(size_t)rr*ldc + cc + 1]   = acc[mt][nt][1] + bp[(size_t)rr*3072 + cc + 1];
                Cb[(size_t)(rr+8)*ldc + cc]   = acc[mt][nt][2] + bp[(size_t)(rr+8)*3072 + cc];
                Cb[(size_t)(rr+8)*ldc + cc+1] = acc[mt][nt][3] + bp[(size_t)(rr+8)*3072 + cc + 1];
            } else {
                float b0 = bp[cc], b1 = bp[cc+1];
                Cb[(size_t)rr*ldc + cc]       = acc[mt][nt][0] + b0;
                Cb[(size_t)rr*ldc + cc + 1]   = acc[mt][nt][1] + b1;
                Cb[(size_t)(rr+8)*ldc + cc]   = acc[mt][nt][2] + b0;
                Cb[(size_t)(rr+8)*ldc + cc+1] = acc[mt][nt][3] + b1;
            }
        }
    }
}

// ---- fully fused decoder step: gemm1 -> attn -> gi -> gru, one launch ----
__global__ void __launch_bounds__(512) k_step(
    const float* __restrict__ Va_w, const float* __restrict__ Va_b,
    const float* __restrict__ out_w, const float* __restrict__ out_b,
    const float* __restrict__ b_ih,
    float* __restrict__ pred_out, float* __restrict__ attn_out, int t)
{
    __shared__ __align__(16) char smraw[40960];
    __shared__ float rp[8][3];
    const int blk = blockIdx.x, tid = threadIdx.x;

    // ---- P1: [q|gh] = hA @ W1^T + b1 (128 blocks, tile map bn=blk>>1, bm=blk&1) ----
    {
        const int bn = (blk >> 1) * 64;
        const int bm = (blk & 1) * 64;
        gemm_phase<0>(tid < 256, g_hA, g_W1 + (size_t)bn*HS, g_qgh + bn, g_b1 + bn, 4096, bm, smraw);
    }
    gsync(3*t + 0);

    // ---- P2: attention (one block per batch, 512 threads) ----
    {
        float* qs = (float*)smraw;
        float* va = qs + HS;
        float* sc = va + HS;
        float* red = sc + SQ;
        float (*part)[128][8] = (float(*)[128][8])(red + 512);
        const int b = blk;
        for (int i = tid; i < HS; i += 512){
            qs[i] = g_qgh[b*4096 + i];
            va[i] = Va_w[i];
        }
        __syncthreads();

        const float vb = Va_b[0];
        const int warp = tid >> 5, lane = tid & 31;
        for (int sr = warp; sr < SQ; sr += 16){
            const __half* up = g_UaK + ((size_t)(b*SQ + sr)) * HS;
            float a0 = 0.f, a1 = 0.f, a2 = 0.f, a3 = 0.f;
#pragma unroll
            for (int j = 0; j < 4; j++){
                int h0 = (j*32 + lane) * 8;
                uint4 v = *(const uint4*)(up + h0);
                const __half2* hp = (const __half2*)&v;
                float4 qa  = *(const float4*)&qs[h0];
                float4 qb  = *(const float4*)&qs[h0+4];
                float4 va0 = *(const float4*)&va[h0];
                float4 va1 = *(const float4*)&va[h0+4];
                float2 f0 = __half22float2(hp[0]);
                float2 f1 = __half22float2(hp[1]);
                float2 f2 = __half22float2(hp[2]);
                float2 f3 = __half22float2(hp[3]);
                a0 += va0.x * tanh_fast(qa.x + f0.x);
                a1 += va0.y * tanh_fast(qa.y + f0.y);
                a2 += va0.z * tanh_fast(qa.z + f1.x);
                a3 += va0.w * tanh_fast(qa.w + f1.y);
                a0 += va1.x * tanh_fast(qb.x + f2.x);
                a1 += va1.y * tanh_fast(qb.y + f2.y);
                a2 += va1.z * tanh_fast(qb.z + f3.x);
                a3 += va1.w * tanh_fast(qb.w + f3.y);
            }
            float acc = (a0 + a1) + (a2 + a3);
#pragma unroll
            for (int o = 16; o; o >>= 1) acc += __shfl_xor_sync(0xffffffffu, acc, o);
            if (lane == 0) sc[sr] = acc + vb;
        }
        __syncthreads();

        // softmax over 512 scores (tid == score index)
        red[tid] = sc[tid]; __syncthreads();
        for (int o = 256; o; o >>= 1){ if (tid < o) red[tid] = fmaxf(red[tid], red[tid+o]); __syncthreads(); }
        float mx = red[0]; __syncthreads();
        float e = __expf(sc[tid] - mx);
        red[tid] = e; __syncthreads();
        for (int o = 256; o; o >>= 1){ if (tid < o) red[tid] += red[tid+o]; __syncthreads(); }
        float w = e * __fdividef(1.f, red[0]);
        __syncthreads();
        sc[tid] = w;
        attn_out[((size_t)b*NT + t)*SQ + tid] = w;
        __syncthreads();

        // context: 4 s-groups x 128 h-threads
        const int si = tid >> 7, hi = tid & 127;
        float acc8[8];
#pragma unroll
        for (int ee = 0; ee < 8; ee++) acc8[ee] = 0.f;
        const __half* ep = g_enc_h + (size_t)b*SQ*HS + hi*8;
#pragma unroll 8
        for (int s = si; s < SQ; s += 4){
            uint4 v = *(const uint4*)(ep + (size_t)s*HS);
            float wv = sc[s];
            const __half2* hp = (const __half2*)&v;
            float2 f;
            f = __half22float2(hp[0]); acc8[0] += wv*f.x; acc8[1] += wv*f.y;
            f = __half22float2(hp[1]); acc8[2] += wv*f.x; acc8[3] += wv*f.y;
            f = __half22float2(hp[2]); acc8[4] += wv*f.x; acc8[5] += wv*f.y;
            f = __half22float2(hp[3]); acc8[6] += wv*f.x; acc8[7] += wv*f.y;
        }
#pragma unroll
        for (int ee = 0; ee < 8; ee++) part[si][hi][ee] = acc8[ee];
        __syncthreads();
        if (tid < 128){
#pragma unroll
            for (int ee = 0; ee < 8; ee++){
                float v = part[0][tid][ee] + part[1][tid][ee] + part[2][tid][ee] + part[3][tid][ee];
                g_ctx[(size_t)b*HS + tid*8 + ee] = __float2half_rn(v);
            }
        }
    }
    gsync(3*t + 1);

    // ---- P3: gi = ctx @ WihC^T + gi_pre (96 of 128 blocks) ----
    {
        const int b3 = (blk < 96) ? blk : 0;
        const int bm = (b3 / 48) * 64;
        const int bn = (b3 % 48) * 64;
        gemm_phase<1>(blk < 96 && tid < 256, g_ctx, g_Wih + (size_t)bn*HS,
                      g_gi + bn, g_gipre + bn, 3072, bm, smraw);
    }
    gsync(3*t + 2);

    // ---- P4: GRU + prediction + next-step gi_pre (one block per batch) ----
    {
        const int b = blk;
        const int warp = tid >> 5, lane = tid & 31;
        if (tid < 256){
            float p0 = 0.f, p1 = 0.f, p2 = 0.f;
#pragma unroll
            for (int j = 0; j < 4; j++){
                int hh = tid + j*256;
                float ir = g_gi[b*3072 + hh];
                float iz = g_gi[b*3072 + 1024 + hh];
                float in = g_gi[b*3072 + 2048 + hh];
                float hr = g_qgh[b*4096 + 1024 + hh];
                float hz = g_qgh[b*4096 + 2048 + hh];
                float hn = g_qgh[b*4096 + 3072 + hh];
                float r = sigmoid_pf(ir + hr);
                float z = sigmoid_pf(iz + hz);
                float n = tanh_precise(in + r*hn);
                float hp = g_h[b*HS + hh];
                float hv = (1.f - z)*n + z*hp;
                g_h [b*HS + hh] = hv;
                g_hA[b*HS + hh] = __float2half_rn(hv);
                p0 += hv * out_w[hh];
                p1 += hv * out_w[1024 + hh];
                p2 += hv * out_w[2048 + hh];
            }
#pragma unroll
            for (int o = 16; o; o >>= 1){
                p0 += __shfl_xor_sync(0xffffffffu, p0, o);
                p1 += __shfl_xor_sync(0xffffffffu, p1, o);
                p2 += __shfl_xor_sync(0xffffffffu, p2, o);
            }
            if (lane == 0){ rp[warp][0] = p0; rp[warp][1] = p1; rp[warp][2] = p2; }
        }
        __syncthreads();
        if (tid < 256){
            float q0 = out_b[0], q1 = out_b[1], q2 = out_b[2];
#pragma unroll
            for (int w = 0; w < 8; w++){ q0 += rp[w][0]; q1 += rp[w][1]; q2 += rp[w][2]; }
            if (tid == 0){
                float mx = fmaxf(q0, fmaxf(q1, q2));
                float l  = logf(__expf(q0-mx) + __expf(q1-mx) + __expf(q2-mx));
                float* po = pred_out + ((size_t)b*NT + t)*3;
                po[0] = q0 - mx - l; po[1] = q1 - mx - l; po[2] = q2 - mx - l;
            }
#pragma unroll
            for (int j = 0; j < 12; j++){
                int n = tid + j*256;
                float w0 = g_W3[n*3], w1 = g_W3[n*3+1], w2 = g_W3[n*3+2];
                g_gipre[b*3072 + n] = b_ih[n] + q0*w0 + q1*w1 + q2*w2;
            }
        }
    }
}

// ---- one-time big GEMM: UaK = enc @ Ua^T + Ua_b (R6-proven: 490us) ----
__global__ void __launch_bounds__(256) gemm_uak(const float* __restrict__ bias)
{
    __shared__ __half As[3][128][40];
    __shared__ __half Bs[3][128][40];
    const __half* A  = g_enc_h;
    const __half* Bm = g_Ua;

    const int bm = blockIdx.y * 128, bn = blockIdx.x * 128;
    const int tid = threadIdx.x, lane = tid & 31, warp = tid >> 5;
    const int wm = warp >> 1, wn = warp & 1;
    const int g = lane >> 2, tc = lane & 3;
    const int r0l = tid >> 2, cl = (tid & 3) * 8;

    float acc[2][8][4];
#pragma unroll
    for (int i=0;i<2;i++)
#pragma unroll
        for (int j=0;j<8;j++)
#pragma unroll
            for (int k=0;k<4;k++) acc[i][j][k] = 0.f;

    const int iters = HS >> 5;
#pragma unroll
    for (int p = 0; p < 2; p++){
        cp16(&As[p][r0l   ][cl], &A [(size_t)(bm + r0l   )*HS + p*32 + cl]);
        cp16(&As[p][r0l+64][cl], &A [(size_t)(bm + r0l+64)*HS + p*32 + cl]);
        cp16(&Bs[p][r0l   ][cl], &Bm[(size_t)(bn + r0l   )*HS + p*32 + cl]);
        cp16(&Bs[p][r0l+64][cl], &Bm[(size_t)(bn + r0l+64)*HS + p*32 + cl]);
        cp_commit();
    }

    int wr = 2;
    for (int i = 0; i < iters; i++){
        if (i + 2 < iters){
            cp16(&As[wr][r0l   ][cl], &A [(size_t)(bm + r0l   )*HS + (i+2)*32 + cl]);
            cp16(&As[wr][r0l+64][cl], &A [(size_t)(bm + r0l+64)*HS + (i+2)*32 + cl]);
            cp16(&Bs[wr][r0l   ][cl], &Bm[(size_t)(bn + r0l   )*HS + (i+2)*32 + cl]);
            cp16(&Bs[wr][r0l+64][cl], &Bm[(size_t)(bn + r0l+64)*HS + (i+2)*32 + cl]);
            cp_commit();
            cp_wait<2>();
            wr = (wr == 2) ? 0 : wr + 1;
        } else {
            cp_wait<0>();
        }
        __syncthreads();
        const int st = i % 3;
#pragma unroll
        for (int ks = 0; ks < 2; ks++){
            uint32_t af[2][4], bf[8][2];
            const int c0 = ks*16 + tc*2;
#pragma unroll
            for (int mt = 0; mt < 2; mt++){
                int rr = wm*32 + mt*16 + g;
                af[mt][0] = *(const uint32_t*)&As[st][rr  ][c0];
                af[mt][1] = *(const uint32_t*)&As[st][rr+8][c0];
                af[mt][2] = *(const uint32_t*)&As[st][rr  ][c0+8];
                af[mt][3] = *(const uint32_t*)&As[st][rr+8][c0+8];
            }
#pragma unroll
            for (int nt = 0; nt < 8; nt++){
                int n0 = wn*64 + nt*8 + g;
                bf[nt][0] = *(const uint32_t*)&Bs[st][n0][c0];
                bf[nt][1] = *(const uint32_t*)&Bs[st][n0][c0+8];
            }
#pragma unroll
            for (int mt = 0; mt < 2; mt++)
#pragma unroll
                for (int nt = 0; nt < 8; nt++)
                    mma16816(acc[mt][nt], af[mt], bf[nt]);
        }
        __syncthreads();
    }

#pragma unroll
    for (int mt = 0; mt < 2; mt++)
#pragma unroll
    for (int nt = 0; nt < 8; nt++){
        int r = bm + wm*32 + mt*16 + g;
        int c = bn + wn*64 + nt*8 + tc*2;
        float b0 = bias[c], b1 = bias[c+1];
        __half2* C = (__half2*)g_UaK;
        C[((size_t)r*HS + c) >> 1]     = __floats2half2_rn(acc[mt][nt][0] + b0, acc[mt][nt][1] + b1);
        C[((size_t)(r+8)*HS + c) >> 1] = __floats2half2_rn(acc[mt][nt][2] + b0, acc[mt][nt][3] + b1);
    }
}

// ---- init / conversion ----
__global__ void k_cvt_enc(const float4* __restrict__ src)
{
    const size_t n = (size_t)BA*SQ*HS/4;
    __half2* d = (__half2*)g_enc_h;
    for (size_t i = blockIdx.x*(size_t)blockDim.x + threadIdx.x; i < n;
         i += (size_t)gridDim.x*blockDim.x){
        float4 v = src[i];
        d[2*i]   = __floats2half2_rn(v.x, v.y);
        d[2*i+1] = __floats2half2_rn(v.z, v.w);
    }
}

__global__ void k_pack_weights(const float* __restrict__ Wa_w, const float* __restrict__ W_hh,
                               const float* __restrict__ Wa_b, const float* __restrict__ b_hh,
                               const float* __restrict__ W_ih, const float* __restrict__ Ua_w)
{
    const int idx = blockIdx.x*blockDim.x + threadIdx.x;
    const int stride = gridDim.x*blockDim.x;
    for (int i = idx; i < 4096*HS; i += stride){
        float v = (i < 1048576) ? Wa_w[i] : W_hh[i - 1048576];
        g_W1[i] = __float2half_rn(v);
    }
    for (int i = idx; i < 3072*HS; i += stride){
        int n = i >> 10, k = i & 1023;
        g_Wih[i] = __float2half_rn(W_ih[n*1027 + 3 + k]);
    }
    for (int i = idx; i < 3072*3; i += stride){
        int n = i / 3, j = i - n*3;
        g_W3[i] = W_ih[n*1027 + j];
    }
    for (int i = idx; i < HS*HS; i += stride) g_Ua[i] = __float2half_rn(Ua_w[i]);
    for (int i = idx; i < 4096; i += stride)  g_b1[i] = (i < 1024) ? Wa_b[i] : b_hh[i - 1024];
}

__global__ void k_init_state(const float* __restrict__ enc_hid, const float* __restrict__ b_ih)
{
    const int idx = blockIdx.x*blockDim.x + threadIdx.x;
    const int stride = gridDim.x*blockDim.x;
    for (int i = idx; i < BA*HS; i += stride){
        float v = enc_hid[i];
        g_h[i]  = v;
        g_hA[i] = __float2half_rn(v);
    }
    for (int i = idx; i < BA*3072; i += stride)
        g_gipre[i] = b_ih[i % 3072];           // pred = SOS = 0
    for (int i = idx; i < 3*NT; i += stride)
        g_bar[i] = 0u;                         // reset grid barriers every replay
}

__global__ void k_copy_hid(float* __restrict__ dst)
{
    const int idx = blockIdx.x*blockDim.x + threadIdx.x;
    if (idx < BA*HS) dst[idx] = g_h[idx];
}

extern "C" void kernel_launch(void* const* d_in, const int* in_sizes, int n_in,
                              void* d_out, int out_size)
{
    (void)in_sizes; (void)n_in; (void)out_size;
    const float* enc      = (const float*)d_in[0];
    const float* enc_hid  = (const float*)d_in[1];
    const float* Wa_w = (const float*)d_in[2];
    const float* Wa_b = (const float*)d_in[3];
    const float* Ua_w = (const float*)d_in[4];
    const float* Ua_b = (const float*)d_in[5];
    const float* Va_w = (const float*)d_in[6];
    const float* Va_b = (const float*)d_in[7];
    const float* W_ih = (const float*)d_in[8];
    const float* b_ih = (const float*)d_in[9];
    const float* W_hh = (const float*)d_in[10];
    const float* b_hh = (const float*)d_in[11];
    const float* out_w = (const float*)d_in[12];
    const float* out_b = (const float*)d_in[13];

    float* pred_out = (float*)d_out;                        // (B, NT, 3)
    float* hid_out  = pred_out + (size_t)BA*NT*3;           // (1, B, H)
    float* attn_out = hid_out  + (size_t)BA*HS;             // (B, NT, SQ)

    k_cvt_enc<<<1184, 256>>>((const float4*)enc);
    k_pack_weights<<<512, 256>>>(Wa_w, W_hh, Wa_b, b_hh, W_ih, Ua_w);
    k_init_state<<<128, 256>>>(enc_hid, b_ih);

    gemm_uak<<<dim3(HS/128, (BA*SQ)/128), 256>>>(Ua_b);

    for (int t = 0; t < NT; t++){
        k_step<<<BA, 512>>>(Va_w, Va_b, out_w, out_b, b_ih, pred_out, attn_out, t);
    }
    k_copy_hid<<<(BA*HS+255)/256, 256>>>(hid_out);
}